// round 14
// baseline (speedup 1.0000x reference)
#include <cuda_runtime.h>
#include <cstdint>

#define NLATC 256
#define NLONC 512
#define MMAXC 256
#define LMAXC 256
#define NBAT  256   // 4*64 flattened batch

// Scratch: Re{F}[b][m][k_lat]. 67 MB. FMASK keeps every access in-bounds.
#define FMASK 0xFFFFFFu
__device__ float g_F[1u << 24];

// ---------------------------------------------------------------------------
// Kernel 1: packed real FFT. Each CTA: 16 real rows (same b, consecutive
// k_lat) as 8 complex 512-pt FFTs (row pair (2r,2r+1) -> re,im).
// Real-input symmetry: 2*ReX_a[m] = ReZ[m]+ReZ[512-m],
//                      2*ReX_b[m] = ImZ[m]+ImZ[512-m].
// Output: per thread 16 contiguous k_lat floats (64B full sectors).
// ---------------------------------------------------------------------------
__global__ __launch_bounds__(256) void sht_fft_kernel(const float* __restrict__ x,
                                                      long long x_elems)
{
    __shared__ float sRe[8][512];
    __shared__ float sIm[8][512];

    const int bid = blockIdx.x;               // 0..4095
    const int b   = bid >> 4;                 // 0..255
    const int kt0 = (bid & 15) << 4;          // 0,16,...,240
    const int tid = (int)(threadIdx.z * blockDim.y * blockDim.x
                        + threadIdx.y * blockDim.x + threadIdx.x); // flat

    // Block-uniform guard (before any __syncthreads).
    if ((long long)(bid + 1) * 8192 > x_elems) return;

    // Load 16 contiguous rows = 8192 floats; even row -> re, odd row -> im.
    const float4* xv = (const float4*)(x + (size_t)bid * 8192);
    for (int i = tid; i < 2048; i += 256) {
        const float4 v = xv[i];
        const int flat = i * 4;
        const int row = flat >> 9;            // 0..15
        const int n   = flat & 511;
        const int r   = row >> 1;
        float* dstp = (row & 1) ? &sIm[r][n] : &sRe[r][n];
        dstp[0] = v.x; dstp[1] = v.y; dstp[2] = v.z; dstp[3] = v.w;
    }
    __syncthreads();

    // Radix-2 DIF, 9 stages; thread owns butterfly tid for all 8 rows.
    #pragma unroll
    for (int span = 256; span >= 1; span >>= 1) {
        const int kk = tid & (span - 1);
        const int i0 = (((tid & ~(span - 1)) << 1) | kk) & 511;
        const int i1 = (i0 + span) & 511;

        float s, c;
        __sincosf(-3.14159265358979323846f * (float)kk / (float)span, &s, &c);

        #pragma unroll
        for (int r = 0; r < 8; r++) {
            const float ar = sRe[r][i0], ai = sIm[r][i0];
            const float br = sRe[r][i1], bi = sIm[r][i1];
            sRe[r][i0] = ar + br;
            sIm[r][i0] = ai + bi;
            const float vr = ar - br, vi = ai - bi;
            sRe[r][i1] = vr * c - vi * s;
            sIm[r][i1] = vr * s + vi * c;
        }
        __syncthreads();
    }

    // DIF storage index s holds Z[brev9(s)]. Thread t takes s2=2t (even s
    // <-> m<256). Conjugate partner Z[(512-m)&511] at index brev9(of it).
    const int s2 = tid * 2;
    const int m  = (int)(__brev((unsigned)s2) >> 23);          // < 256
    const int mn = (512 - m) & 511;
    const int in = (int)(__brev((unsigned)mn) >> 23) & 511;
    const float hs = 0.5f * (6.283185307179586f / 512.0f);

    float f[16];
    #pragma unroll
    for (int r = 0; r < 8; r++) {
        f[2 * r]     = hs * (sRe[r][s2] + sRe[r][in]);   // row 2r   (x_a)
        f[2 * r + 1] = hs * (sIm[r][s2] + sIm[r][in]);   // row 2r+1 (x_b)
    }

    float4* dst = (float4*)&g_F[((unsigned)(b * 256 + m) * 256 + kt0) & FMASK];
    #pragma unroll
    for (int q = 0; q < 4; q++)
        dst[q] = make_float4(f[4 * q], f[4 * q + 1], f[4 * q + 2], f[4 * q + 3]);
}

// ---------------------------------------------------------------------------
// Kernel 2: out[b][l][m] = sum_{k<256} F[b][k][m] * W[m][l][k]
// Parity: w[m,l,255-k] = (-1)^{l+m} w[m,l,k] ->
//   out = sum_{k<128} w[m,l,k] * ( F[k] + (-1)^{l+m} F[255-k] )
// CTA = (m, l-tile 64). Thread: 4 consecutive b (float4) x 8 l.
// Inner loop: 4x LDS.128 : 32 FMA.
// ---------------------------------------------------------------------------
__global__ __launch_bounds__(256) void sht_leg_kernel(const float* __restrict__ w,
                                                      float* __restrict__ outf,
                                                      long long w_elems,
                                                      long long out_elems)
{
    const int m   = blockIdx.x;           // 0..255
    const int l0  = blockIdx.y * 64;      // 0,64,128,192
    const int tid = (int)(threadIdx.z * blockDim.y * blockDim.x
                        + threadIdx.y * blockDim.x + threadIdx.x); // flat 0..255

    // ---- pure-zero tile fast path (weight exactly zero for l < m) ----
    if (l0 + 64 <= m) {
        for (int i = tid; i < 256 * 64; i += 256) {
            const int b = i >> 6;
            const int l = l0 + (i & 63);
            const long long oi = ((long long)b * 256 + l) * 256 + m;
            if (oi < out_elems) outf[oi] = 0.0f;
        }
        return;
    }

    __shared__ float sW [32][68];         // [k][l]  68 floats: 16B-aligned rows
    __shared__ float sFe[32][132];        // [k][b]  even part
    __shared__ float sFo[32][132];        // [k][b]  odd part

    const int tx = tid & 31;              // b4 = tx*4
    const int ty = tid >> 5;              // l = l0 + ty*8 + j, j=0..7

    // Parity of (l+m) at j=0; alternates with j (warp-uniform pointer swap).
    const int p0 = (l0 + ty * 8 + m) & 1;
    const float* Fa = p0 ? &sFo[0][0] : &sFe[0][0];   // feeds even j
    const float* Fb = p0 ? &sFe[0][0] : &sFo[0][0];   // feeds odd j

    for (int b0 = 0; b0 < 256; b0 += 128) {
        float4 acc[8];
        #pragma unroll
        for (int j = 0; j < 8; j++) acc[j] = make_float4(0.f, 0.f, 0.f, 0.f);

        for (int k0 = 0; k0 < 128; k0 += 32) {
            __syncthreads();
            // W tile: 32 k x 64 l (gmem coalesced over k).
            for (int i = tid; i < 32 * 64; i += 256) {
                const int k = i & 31, l = i >> 5;
                const long long wi = ((long long)m * 256 + (l0 + l)) * 256 + (k0 + k);
                sW[k][l] = (wi < w_elems) ? w[wi] : 0.0f;
            }
            // F tiles: 128 b x 32 k; build even/odd parts.
            for (int i = tid; i < 128 * 32; i += 256) {
                const int b = i >> 5, k = i & 31;
                const unsigned base = (unsigned)(((b0 + b) * 256 + m) * 256);
                const float lo = g_F[(base + (k0 + k)) & FMASK];
                const float hi = g_F[(base + (255 - k0 - k)) & FMASK];
                sFe[k][b] = lo + hi;
                sFo[k][b] = lo - hi;
            }
            __syncthreads();

            #pragma unroll
            for (int k = 0; k < 32; k++) {
                const float4 fa  = *(const float4*)(Fa + k * 132 + tx * 4);
                const float4 fb  = *(const float4*)(Fb + k * 132 + tx * 4);
                const float4 wv0 = *(const float4*)(&sW[k][ty * 8]);
                const float4 wv1 = *(const float4*)(&sW[k][ty * 8 + 4]);
                acc[0].x += wv0.x * fa.x; acc[0].y += wv0.x * fa.y;
                acc[0].z += wv0.x * fa.z; acc[0].w += wv0.x * fa.w;
                acc[1].x += wv0.y * fb.x; acc[1].y += wv0.y * fb.y;
                acc[1].z += wv0.y * fb.z; acc[1].w += wv0.y * fb.w;
                acc[2].x += wv0.z * fa.x; acc[2].y += wv0.z * fa.y;
                acc[2].z += wv0.z * fa.z; acc[2].w += wv0.z * fa.w;
                acc[3].x += wv0.w * fb.x; acc[3].y += wv0.w * fb.y;
                acc[3].z += wv0.w * fb.z; acc[3].w += wv0.w * fb.w;
                acc[4].x += wv1.x * fa.x; acc[4].y += wv1.x * fa.y;
                acc[4].z += wv1.x * fa.z; acc[4].w += wv1.x * fa.w;
                acc[5].x += wv1.y * fb.x; acc[5].y += wv1.y * fb.y;
                acc[5].z += wv1.y * fb.z; acc[5].w += wv1.y * fb.w;
                acc[6].x += wv1.z * fa.x; acc[6].y += wv1.z * fa.y;
                acc[6].z += wv1.z * fa.z; acc[6].w += wv1.z * fa.w;
                acc[7].x += wv1.w * fb.x; acc[7].y += wv1.w * fb.y;
                acc[7].z += wv1.w * fb.z; acc[7].w += wv1.w * fb.w;
            }
        }

        // Store (guarded in float32 output elements).
        #pragma unroll
        for (int j = 0; j < 8; j++) {
            const int l = l0 + ty * 8 + j;
            const float av[4] = {acc[j].x, acc[j].y, acc[j].z, acc[j].w};
            #pragma unroll
            for (int c = 0; c < 4; c++) {
                const int b = b0 + tx * 4 + c;
                const long long oi = ((long long)b * 256 + l) * 256 + m;
                if (oi < out_elems) outf[oi] = av[c];
            }
        }
        __syncthreads();
    }
}

// ---------------------------------------------------------------------------
extern "C" void kernel_launch(void* const* d_in, const int* in_sizes, int n_in,
                              void* d_out, int out_size)
{
    if (n_in < 2 || d_in == nullptr || d_out == nullptr || in_sizes == nullptr)
        return;
    if (d_in[0] == nullptr || d_in[1] == nullptr) return;

    // x (33.5M elems) is 2x weight (16.7M): larger of the first two -> x.
    int xi = 0, wi = 1;
    if ((long long)in_sizes[1] > (long long)in_sizes[0]) { xi = 1; wi = 0; }

    const float* x = (const float*)d_in[xi];
    const float* w = (const float*)d_in[wi];
    const long long x_elems = (long long)in_sizes[xi];
    const long long w_elems = (long long)in_sizes[wi];

    float* outf = (float*)d_out;
    const long long out_elems = (long long)out_size;  // float32 elements

    sht_fft_kernel<<<NBAT * 16, 256>>>(x, x_elems);   // 16 k_lat rows per CTA
    sht_leg_kernel<<<dim3(MMAXC, LMAXC / 64), 256>>>(w, outf, w_elems, out_elems);
}

// round 15
// speedup vs baseline: 1.5223x; 1.5223x over previous
#include <cuda_runtime.h>
#include <cstdint>

#define NLATC 256
#define NLONC 512
#define MMAXC 256
#define LMAXC 256
#define NBAT  256   // 4*64 flattened batch

// Scratch: Re{F}[b][m][k_lat]. 67 MB. FMASK keeps every access in-bounds.
#define FMASK 0xFFFFFFu
__device__ float g_F[1u << 24];

// ---------------------------------------------------------------------------
// Kernel 1: packed real FFT. Each CTA: 16 real rows (same b, consecutive
// k_lat) as 8 complex 512-pt FFTs (row pair (2r,2r+1) -> re,im).
// 2*ReX_a[m] = ReZ[m]+ReZ[512-m],  2*ReX_b[m] = ImZ[m]+ImZ[512-m].
// Output: per thread 16 contiguous k_lat floats (64B full sectors).
// ---------------------------------------------------------------------------
__global__ __launch_bounds__(256) void sht_fft_kernel(const float* __restrict__ x,
                                                      long long x_elems)
{
    __shared__ float sRe[8][512];
    __shared__ float sIm[8][512];

    const int bid = blockIdx.x;               // 0..4095
    const int b   = bid >> 4;                 // 0..255
    const int kt0 = (bid & 15) << 4;          // 0,16,...,240
    const int tid = (int)(threadIdx.z * blockDim.y * blockDim.x
                        + threadIdx.y * blockDim.x + threadIdx.x); // flat

    if ((long long)(bid + 1) * 8192 > x_elems) return;   // block-uniform

    const float4* xv = (const float4*)(x + (size_t)bid * 8192);
    for (int i = tid; i < 2048; i += 256) {
        const float4 v = xv[i];
        const int flat = i * 4;
        const int row = flat >> 9;            // 0..15
        const int n   = flat & 511;
        const int r   = row >> 1;
        float* dstp = (row & 1) ? &sIm[r][n] : &sRe[r][n];
        dstp[0] = v.x; dstp[1] = v.y; dstp[2] = v.z; dstp[3] = v.w;
    }
    __syncthreads();

    #pragma unroll
    for (int span = 256; span >= 1; span >>= 1) {
        const int kk = tid & (span - 1);
        const int i0 = (((tid & ~(span - 1)) << 1) | kk) & 511;
        const int i1 = (i0 + span) & 511;

        float s, c;
        __sincosf(-3.14159265358979323846f * (float)kk / (float)span, &s, &c);

        #pragma unroll
        for (int r = 0; r < 8; r++) {
            const float ar = sRe[r][i0], ai = sIm[r][i0];
            const float br = sRe[r][i1], bi = sIm[r][i1];
            sRe[r][i0] = ar + br;
            sIm[r][i0] = ai + bi;
            const float vr = ar - br, vi = ai - bi;
            sRe[r][i1] = vr * c - vi * s;
            sIm[r][i1] = vr * s + vi * c;
        }
        __syncthreads();
    }

    const int s2 = tid * 2;
    const int m  = (int)(__brev((unsigned)s2) >> 23);          // < 256
    const int mn = (512 - m) & 511;
    const int in = (int)(__brev((unsigned)mn) >> 23) & 511;
    const float hs = 0.5f * (6.283185307179586f / 512.0f);

    float f[16];
    #pragma unroll
    for (int r = 0; r < 8; r++) {
        f[2 * r]     = hs * (sRe[r][s2] + sRe[r][in]);   // row 2r   (x_a)
        f[2 * r + 1] = hs * (sIm[r][s2] + sIm[r][in]);   // row 2r+1 (x_b)
    }

    float4* dst = (float4*)&g_F[((unsigned)(b * 256 + m) * 256 + kt0) & FMASK];
    #pragma unroll
    for (int q = 0; q < 4; q++)
        dst[q] = make_float4(f[4 * q], f[4 * q + 1], f[4 * q + 2], f[4 * q + 3]);
}

// ---------------------------------------------------------------------------
// Kernel 2: out[b][l][m] = sum_{k<256} F[b][k][m] * W[m][l][k]
// Parity: out = sum_{k<128} w[m,l,k] * ( F[k] + (-1)^{l+m} F[255-k] )
// CTA = (m, l-tile 64), 512 threads. Per-thread 4b x 4l (R13 proven shape).
// k-chunk 64 (half the syncs of R13); F staging amortized over 64 l.
// ---------------------------------------------------------------------------
__global__ __launch_bounds__(512) void sht_leg_kernel(const float* __restrict__ w,
                                                      float* __restrict__ outf,
                                                      long long w_elems,
                                                      long long out_elems)
{
    const int m   = blockIdx.x;           // 0..255
    const int l0  = blockIdx.y * 64;      // 0,64,128,192
    const int tid = (int)(threadIdx.z * blockDim.y * blockDim.x
                        + threadIdx.y * blockDim.x + threadIdx.x); // flat 0..511

    // ---- pure-zero tile fast path (weight exactly zero for l < m) ----
    if (l0 + 64 <= m) {
        for (int i = tid; i < 256 * 64; i += 512) {
            const int b = i >> 6;
            const int l = l0 + (i & 63);
            const long long oi = ((long long)b * 256 + l) * 256 + m;
            if (oi < out_elems) outf[oi] = 0.0f;
        }
        return;
    }

    __shared__ float sW [64][68];         // [k][l]  68: 16B-aligned rows
    __shared__ float sFe[64][132];        // [k][b]  even part
    __shared__ float sFo[64][132];        // [k][b]  odd part

    const int tx = tid & 31;              // b4 = tx*4 (4 consecutive b)
    const int ty = tid >> 5;              // 0..15 : l = l0 + ty*4 + j

    // Parity of (l+m) at j=0; alternates with j. Warp-uniform pointer swap.
    const int p0 = (l0 + ty * 4 + m) & 1;
    const float* Fa = p0 ? &sFo[0][0] : &sFe[0][0];   // feeds even j
    const float* Fb = p0 ? &sFe[0][0] : &sFo[0][0];   // feeds odd j

    for (int b0 = 0; b0 < 256; b0 += 128) {
        float4 acc[4];
        #pragma unroll
        for (int j = 0; j < 4; j++) acc[j] = make_float4(0.f, 0.f, 0.f, 0.f);

        for (int k0 = 0; k0 < 128; k0 += 64) {
            __syncthreads();
            // W tile: 64 k x 64 l (gmem coalesced over k).
            for (int i = tid; i < 64 * 64; i += 512) {
                const int k = i & 63, l = i >> 6;
                const long long wi = ((long long)m * 256 + (l0 + l)) * 256 + (k0 + k);
                sW[k][l] = (wi < w_elems) ? w[wi] : 0.0f;
            }
            // F tiles: 128 b x 64 k; build even/odd parts.
            for (int i = tid; i < 128 * 64; i += 512) {
                const int b = i >> 6, k = i & 63;
                const unsigned base = (unsigned)(((b0 + b) * 256 + m) * 256);
                const float lo = g_F[(base + (k0 + k)) & FMASK];
                const float hi = g_F[(base + (255 - k0 - k)) & FMASK];
                sFe[k][b] = lo + hi;
                sFo[k][b] = lo - hi;
            }
            __syncthreads();

            #pragma unroll 8
            for (int k = 0; k < 64; k++) {
                const float4 fa = *(const float4*)(Fa + k * 132 + tx * 4);
                const float4 fb = *(const float4*)(Fb + k * 132 + tx * 4);
                const float4 wv = *(const float4*)(&sW[k][ty * 4]);
                acc[0].x += wv.x * fa.x; acc[0].y += wv.x * fa.y;
                acc[0].z += wv.x * fa.z; acc[0].w += wv.x * fa.w;
                acc[1].x += wv.y * fb.x; acc[1].y += wv.y * fb.y;
                acc[1].z += wv.y * fb.z; acc[1].w += wv.y * fb.w;
                acc[2].x += wv.z * fa.x; acc[2].y += wv.z * fa.y;
                acc[2].z += wv.z * fa.z; acc[2].w += wv.z * fa.w;
                acc[3].x += wv.w * fb.x; acc[3].y += wv.w * fb.y;
                acc[3].z += wv.w * fb.z; acc[3].w += wv.w * fb.w;
            }
        }

        // Store (guarded in float32 output elements).
        #pragma unroll
        for (int j = 0; j < 4; j++) {
            const int l = l0 + ty * 4 + j;
            const float av[4] = {acc[j].x, acc[j].y, acc[j].z, acc[j].w};
            #pragma unroll
            for (int c = 0; c < 4; c++) {
                const int b = b0 + tx * 4 + c;
                const long long oi = ((long long)b * 256 + l) * 256 + m;
                if (oi < out_elems) outf[oi] = av[c];
            }
        }
        __syncthreads();
    }
}

// ---------------------------------------------------------------------------
extern "C" void kernel_launch(void* const* d_in, const int* in_sizes, int n_in,
                              void* d_out, int out_size)
{
    if (n_in < 2 || d_in == nullptr || d_out == nullptr || in_sizes == nullptr)
        return;
    if (d_in[0] == nullptr || d_in[1] == nullptr) return;

    // x (33.5M elems) is 2x weight (16.7M): larger of the first two -> x.
    int xi = 0, wi = 1;
    if ((long long)in_sizes[1] > (long long)in_sizes[0]) { xi = 1; wi = 0; }

    const float* x = (const float*)d_in[xi];
    const float* w = (const float*)d_in[wi];
    const long long x_elems = (long long)in_sizes[xi];
    const long long w_elems = (long long)in_sizes[wi];

    float* outf = (float*)d_out;
    const long long out_elems = (long long)out_size;  // float32 elements

    sht_fft_kernel<<<NBAT * 16, 256>>>(x, x_elems);   // 16 k_lat rows per CTA
    sht_leg_kernel<<<dim3(MMAXC, LMAXC / 64), 512>>>(w, outf, w_elems, out_elems);
}